// round 2
// baseline (speedup 1.0000x reference)
#include <cuda_runtime.h>
#include <math.h>

#define NN 50000
#define EE 500000

// Scratch (no cudaMalloc allowed): node latents, edge latents, aggregated messages.
__device__ float g_nh[NN * 128];
__device__ float g_eh[EE * 128];
__device__ float g_recv[NN * 128];

__device__ __forceinline__ float gelu_f(float x) {
    // jax.nn.gelu default (approximate=True): tanh form
    return 0.5f * x * (1.0f + tanhf(0.7978845608028654f * (x + 0.044715f * x * x * x)));
}

// MODE: 0 = embed nodes (K=7 -> g_nh), 1 = embed edges (K=3 -> g_eh)
//       2 = edge update (concat 386 -> MLP -> atomic scatter + residual+LN on eh)
//       3 = node update (concat 258 -> MLP -> residual+LN on nh)
//       4 = decoder (nh -> MLP -> out[N,3])
template <int MODE>
__global__ __launch_bounds__(256, 2)
void gnet_kernel(const float* __restrict__ A0,
                 const float* __restrict__ W0, const float* __restrict__ b0,
                 const float* __restrict__ W1, const float* __restrict__ b1,
                 const float* __restrict__ glob,
                 const int* __restrict__ senders, const int* __restrict__ receivers,
                 const float* __restrict__ ln_s, const float* __restrict__ ln_b,
                 float* __restrict__ outp, int nrows)
{
    extern __shared__ float sm[];
    float* Hs  = sm;            // 128 x 132 (padded) = 16896 floats
    float* As  = sm + 16896;    // 128 x 16 = 2048
    float* Ws  = sm + 18944;    // 16 x 128 = 2048
    float* scs = sm + 20992;    // 128
    float* bss = sm + 21120;    // 128
    int*   sidx = (int*)(sm + 21248);  // 128
    int*   ridx = (int*)(sm + 21376);  // 128

    const int tid = threadIdx.x;
    const int tx = tid & 15;
    const int ty = tid >> 4;
    const int r0 = blockIdx.x * 128;

    if (MODE == 2 && tid < 128) {
        int e = r0 + tid; if (e >= nrows) e = nrows - 1;
        sidx[tid] = senders[e];
        ridx[tid] = receivers[e];
    }
    if ((MODE == 2 || MODE == 3) && tid < 128) {
        scs[tid] = ln_s[tid];
        bss[tid] = ln_b[tid];
    }

    float acc[8][8];
    #pragma unroll
    for (int i = 0; i < 8; i++)
        #pragma unroll
        for (int j = 0; j < 8; j++) acc[i][j] = 0.f;

    // ---------------- Layer 1 ----------------
    if (MODE == 0 || MODE == 1) {
        const int KIN = (MODE == 0) ? 7 : 3;
        if (tid < 128) {
            int rg = r0 + tid; if (rg >= nrows) rg = nrows - 1;
            #pragma unroll
            for (int k = 0; k < 8; k++)
                As[tid * 8 + k] = (k < KIN) ? A0[rg * KIN + k] : 0.f;
        }
        #pragma unroll
        for (int q = 0; q < 4; q++) {
            int idx = tid + 256 * q;
            Ws[idx] = (idx < KIN * 128) ? W0[idx] : 0.f;
        }
        __syncthreads();
        #pragma unroll
        for (int kk = 0; kk < 8; kk++) {
            float a[8], w[8];
            #pragma unroll
            for (int i = 0; i < 8; i++) a[i] = As[(ty + 16 * i) * 8 + kk];
            #pragma unroll
            for (int j = 0; j < 8; j++) w[j] = Ws[kk * 128 + tx + 16 * j];
            #pragma unroll
            for (int i = 0; i < 8; i++)
                #pragma unroll
                for (int j = 0; j < 8; j++) acc[i][j] += a[i] * w[j];
        }
    } else {
        const int NT = (MODE == 2) ? 24 : ((MODE == 3) ? 16 : 8);
        const int row = tid >> 1, half = tid & 1;
        int rg = r0 + row; if (rg >= nrows) rg = nrows - 1;
        for (int kt = 0; kt < NT; kt++) {
            __syncthreads();
            {
                const int k0 = kt * 16;
                const float* src;
                if (MODE == 2) {
                    if (kt < 8)       src = &g_eh[(size_t)rg * 128 + k0];
                    else if (kt < 16) src = &g_nh[sidx[row] * 128 + (k0 - 128)];
                    else              src = &g_nh[ridx[row] * 128 + (k0 - 256)];
                } else if (MODE == 3) {
                    if (kt < 8)       src = &g_nh[rg * 128 + k0];
                    else              src = &g_recv[rg * 128 + (k0 - 128)];
                } else {
                    src = &g_nh[rg * 128 + k0];
                }
                *(float4*)&As[row * 16 + half * 8]     = *(const float4*)(src + half * 8);
                *(float4*)&As[row * 16 + half * 8 + 4] = *(const float4*)(src + half * 8 + 4);
                const int kr = tid >> 4, seg = tid & 15;
                const float* wsrc = &W0[(k0 + kr) * 128 + seg * 8];
                *(float4*)&Ws[kr * 128 + seg * 8]     = *(const float4*)wsrc;
                *(float4*)&Ws[kr * 128 + seg * 8 + 4] = *(const float4*)(wsrc + 4);
            }
            __syncthreads();
            #pragma unroll
            for (int kk = 0; kk < 16; kk++) {
                float a[8], w[8];
                #pragma unroll
                for (int i = 0; i < 8; i++) a[i] = As[(ty + 16 * i) * 16 + kk];
                #pragma unroll
                for (int j = 0; j < 8; j++) w[j] = Ws[kk * 128 + tx + 16 * j];
                #pragma unroll
                for (int i = 0; i < 8; i++)
                    #pragma unroll
                    for (int j = 0; j < 8; j++) acc[i][j] += a[i] * w[j];
            }
        }
        if (MODE == 2 || MODE == 3) {
            const int kg = (MODE == 2) ? 384 : 256;  // globals columns in concat
            float g0 = glob[0], g1 = glob[1];
            #pragma unroll
            for (int j = 0; j < 8; j++) {
                int c = tx + 16 * j;
                float d = g0 * W0[kg * 128 + c] + g1 * W0[(kg + 1) * 128 + c];
                #pragma unroll
                for (int i = 0; i < 8; i++) acc[i][j] += d;
            }
        }
    }

    // bias + gelu -> Hs
    __syncthreads();
    #pragma unroll
    for (int j = 0; j < 8; j++) {
        int c = tx + 16 * j;
        float bb = b0[c];
        #pragma unroll
        for (int i = 0; i < 8; i++)
            Hs[(ty + 16 * i) * 132 + c] = gelu_f(acc[i][j] + bb);
    }

    // ---------------- Layer 2 ----------------
    #pragma unroll
    for (int i = 0; i < 8; i++)
        #pragma unroll
        for (int j = 0; j < 8; j++) acc[i][j] = 0.f;

    if (MODE == 4) {
        __syncthreads();
        for (int idx = tid; idx < 384; idx += 256) Ws[idx] = W1[idx];  // [128,3]
        __syncthreads();
        for (int idx = tid; idx < 384; idx += 256) {
            int rr = idx / 3, o = idx % 3;
            float s = b1[o];
            #pragma unroll 8
            for (int k = 0; k < 128; k++) s += Hs[rr * 132 + k] * Ws[k * 3 + o];
            int rg2 = r0 + rr;
            if (rg2 < nrows) outp[rg2 * 3 + o] = s;
        }
        return;
    }

    for (int kt = 0; kt < 8; kt++) {
        __syncthreads();
        {
            const int k0 = kt * 16;
            const int kr = tid >> 4, seg = tid & 15;
            const float* wsrc = &W1[(k0 + kr) * 128 + seg * 8];
            *(float4*)&Ws[kr * 128 + seg * 8]     = *(const float4*)wsrc;
            *(float4*)&Ws[kr * 128 + seg * 8 + 4] = *(const float4*)(wsrc + 4);
        }
        __syncthreads();
        const int k0 = kt * 16;
        #pragma unroll
        for (int kk = 0; kk < 16; kk++) {
            float a[8], w[8];
            #pragma unroll
            for (int i = 0; i < 8; i++) a[i] = Hs[(ty + 16 * i) * 132 + k0 + kk];
            #pragma unroll
            for (int j = 0; j < 8; j++) w[j] = Ws[kk * 128 + tx + 16 * j];
            #pragma unroll
            for (int i = 0; i < 8; i++)
                #pragma unroll
                for (int j = 0; j < 8; j++) acc[i][j] += a[i] * w[j];
        }
    }
    __syncthreads();

    if (MODE == 0 || MODE == 1) {
        float* dst = (MODE == 0) ? g_nh : g_eh;
        #pragma unroll
        for (int i = 0; i < 8; i++) {
            int r = ty + 16 * i, rg2 = r0 + r;
            if (rg2 < nrows) {
                #pragma unroll
                for (int j = 0; j < 8; j++) {
                    int c = tx + 16 * j;
                    dst[(size_t)rg2 * 128 + c] = acc[i][j] + b1[c];
                }
            }
        }
        return;
    }

    // MODE 2/3: new value + residual into Hs; edge mode also scatters to recv
    #pragma unroll
    for (int i = 0; i < 8; i++) {
        int r = ty + 16 * i, rg2 = r0 + r;
        if (rg2 < nrows) {
            #pragma unroll
            for (int j = 0; j < 8; j++) {
                int c = tx + 16 * j;
                float val = acc[i][j] + b1[c];
                if (MODE == 2) {
                    atomicAdd(&g_recv[ridx[r] * 128 + c], val);
                    Hs[r * 132 + c] = g_eh[(size_t)rg2 * 128 + c] + val;
                } else {
                    Hs[r * 132 + c] = g_nh[rg2 * 128 + c] + val;
                }
            }
        }
    }
    __syncthreads();

    // Fused LayerNorm over each 128-wide row
    const int warp = tid >> 5, lane = tid & 31;
    for (int rr = warp; rr < 128; rr += 8) {
        int rg2 = r0 + rr;
        float4 v = *(float4*)&Hs[rr * 132 + lane * 4];
        float s = v.x + v.y + v.z + v.w;
        #pragma unroll
        for (int o = 16; o > 0; o >>= 1) s += __shfl_xor_sync(0xffffffffu, s, o);
        float mean = s * (1.f / 128.f);
        float dx = v.x - mean, dy = v.y - mean, dz = v.z - mean, dw = v.w - mean;
        float q = dx * dx + dy * dy + dz * dz + dw * dw;
        #pragma unroll
        for (int o = 16; o > 0; o >>= 1) q += __shfl_xor_sync(0xffffffffu, q, o);
        float inv = rsqrtf(q * (1.f / 128.f) + 1e-6f);
        float4 sc = *(float4*)&scs[lane * 4];
        float4 bb = *(float4*)&bss[lane * 4];
        float4 o4;
        o4.x = dx * inv * sc.x + bb.x;
        o4.y = dy * inv * sc.y + bb.y;
        o4.z = dz * inv * sc.z + bb.z;
        o4.w = dw * inv * sc.w + bb.w;
        if (rg2 < nrows) {
            float* dst = (MODE == 2) ? &g_eh[(size_t)rg2 * 128] : &g_nh[rg2 * 128];
            *(float4*)&dst[lane * 4] = o4;
        }
    }
}

__global__ void zero_recv_kernel() {
    int i = blockIdx.x * blockDim.x + threadIdx.x;
    if (i < NN * 128) g_recv[i] = 0.f;
}

extern "C" void kernel_launch(void* const* d_in, const int* in_sizes, int n_in,
                              void* d_out, int out_size)
{
    const float* nodes   = (const float*)d_in[0];
    const float* edges   = (const float*)d_in[1];
    const float* glob    = (const float*)d_in[2];
    const int*   senders = (const int*)d_in[3];
    const int*   recvrs  = (const int*)d_in[4];
    const float* ne_W0 = (const float*)d_in[5],  *ne_b0 = (const float*)d_in[6];
    const float* ne_W1 = (const float*)d_in[7],  *ne_b1 = (const float*)d_in[8];
    const float* ee_W0 = (const float*)d_in[9],  *ee_b0 = (const float*)d_in[10];
    const float* ee_W1 = (const float*)d_in[11], *ee_b1 = (const float*)d_in[12];
    const float* eu_W0 = (const float*)d_in[13], *eu_b0 = (const float*)d_in[14];
    const float* eu_W1 = (const float*)d_in[15], *eu_b1 = (const float*)d_in[16];
    const float* nu_W0 = (const float*)d_in[17], *nu_b0 = (const float*)d_in[18];
    const float* nu_W1 = (const float*)d_in[19], *nu_b1 = (const float*)d_in[20];
    const float* ln_s  = (const float*)d_in[21], *ln_b  = (const float*)d_in[22];
    const float* dc_W0 = (const float*)d_in[23], *dc_b0 = (const float*)d_in[24];
    const float* dc_W1 = (const float*)d_in[25], *dc_b1 = (const float*)d_in[26];
    float* out = (float*)d_out;

    const int SMEM = 21504 * (int)sizeof(float);  // 86016 B dynamic smem
    cudaFuncSetAttribute(gnet_kernel<0>, cudaFuncAttributeMaxDynamicSharedMemorySize, SMEM);
    cudaFuncSetAttribute(gnet_kernel<1>, cudaFuncAttributeMaxDynamicSharedMemorySize, SMEM);
    cudaFuncSetAttribute(gnet_kernel<2>, cudaFuncAttributeMaxDynamicSharedMemorySize, SMEM);
    cudaFuncSetAttribute(gnet_kernel<3>, cudaFuncAttributeMaxDynamicSharedMemorySize, SMEM);
    cudaFuncSetAttribute(gnet_kernel<4>, cudaFuncAttributeMaxDynamicSharedMemorySize, SMEM);

    const int gN = (NN + 127) / 128;   // 391
    const int gE = (EE + 127) / 128;   // 3907

    // Embeds
    gnet_kernel<0><<<gN, 256, SMEM>>>(nodes, ne_W0, ne_b0, ne_W1, ne_b1,
                                      nullptr, nullptr, nullptr, nullptr, nullptr, nullptr, NN);
    gnet_kernel<1><<<gE, 256, SMEM>>>(edges, ee_W0, ee_b0, ee_W1, ee_b1,
                                      nullptr, nullptr, nullptr, nullptr, nullptr, nullptr, EE);

    // Message-passing steps
    for (int s = 0; s < 2; s++) {
        zero_recv_kernel<<<(NN * 128 + 255) / 256, 256>>>();
        gnet_kernel<2><<<gE, 256, SMEM>>>(nullptr,
                                          eu_W0 + s * 386 * 128, eu_b0 + s * 128,
                                          eu_W1 + s * 128 * 128, eu_b1 + s * 128,
                                          glob, senders, recvrs, ln_s, ln_b, nullptr, EE);
        gnet_kernel<3><<<gN, 256, SMEM>>>(nullptr,
                                          nu_W0 + s * 258 * 128, nu_b0 + s * 128,
                                          nu_W1 + s * 128 * 128, nu_b1 + s * 128,
                                          glob, nullptr, nullptr, ln_s, ln_b, nullptr, NN);
    }

    // Decoder
    gnet_kernel<4><<<gN, 256, SMEM>>>(nullptr, dc_W0, dc_b0, dc_W1, dc_b1,
                                      nullptr, nullptr, nullptr, nullptr, nullptr, out, NN);
}

// round 4
// speedup vs baseline: 1.1046x; 1.1046x over previous
#include <cuda_runtime.h>

#define NN 50000
#define EE 500000

// Scratch (no cudaMalloc allowed): node latents, edge latents, aggregated messages.
__device__ float g_nh[NN * 128];
__device__ float g_eh[EE * 128];
__device__ float g_recv[NN * 128];

typedef unsigned long long ull;

__device__ __forceinline__ ull dup2(float x) {
    ull r; asm("mov.b64 %0, {%1, %1};" : "=l"(r) : "f"(x)); return r;
}
__device__ __forceinline__ void fma2(ull &d, ull a, ull b) {
    asm("fma.rn.f32x2 %0, %1, %2, %0;" : "+l"(d) : "l"(a), "l"(b));
}
__device__ __forceinline__ float2 unpk(ull v) {
    float2 f; asm("mov.b64 {%0, %1}, %2;" : "=f"(f.x), "=f"(f.y) : "l"(v)); return f;
}

__device__ __forceinline__ float gelu_f(float x) {
    // jax.nn.gelu tanh form; HW tanh.approx (err ~1e-4, renormalized by LN)
    float u = 0.7978845608028654f * (x + 0.044715f * x * x * x);
    float t; asm("tanh.approx.f32 %0, %1;" : "=f"(t) : "f"(u));
    return 0.5f * x * (1.0f + t);
}

// A-tile transposed in smem: As_t[k][row] (128 rows). W tile: Ws[k][col].
template <int KK>
__device__ __forceinline__ void mma_kt(const float* __restrict__ As_t,
                                       const float* __restrict__ Ws,
                                       ull (&acc)[8][4], int rbase, int cbase) {
    #pragma unroll
    for (int kk = 0; kk < KK; kk++) {
        float4 a0 = *(const float4*)&As_t[kk * 128 + rbase];
        float4 a1 = *(const float4*)&As_t[kk * 128 + rbase + 4];
        ulonglong2 wl0 = *(const ulonglong2*)&Ws[kk * 128 + cbase];
        ulonglong2 wl1 = *(const ulonglong2*)&Ws[kk * 128 + cbase + 4];
        ull w2[4] = {wl0.x, wl0.y, wl1.x, wl1.y};
        float av[8] = {a0.x, a0.y, a0.z, a0.w, a1.x, a1.y, a1.z, a1.w};
        #pragma unroll
        for (int i = 0; i < 8; i++) {
            ull ad = dup2(av[i]);
            #pragma unroll
            for (int j = 0; j < 4; j++) fma2(acc[i][j], ad, w2[j]);
        }
    }
}

// Layer-2 variant: A read row-major from Hs (stride 132, broadcast across half-warp)
__device__ __forceinline__ void mma_kt_h(const float* __restrict__ Hs,
                                         const float* __restrict__ Ws,
                                         ull (&acc)[8][4], int rbase, int cbase, int k0) {
    #pragma unroll
    for (int kk = 0; kk < 16; kk++) {
        ulonglong2 wl0 = *(const ulonglong2*)&Ws[kk * 128 + cbase];
        ulonglong2 wl1 = *(const ulonglong2*)&Ws[kk * 128 + cbase + 4];
        ull w2[4] = {wl0.x, wl0.y, wl1.x, wl1.y};
        #pragma unroll
        for (int i = 0; i < 8; i++) {
            ull ad = dup2(Hs[(rbase + i) * 132 + k0 + kk]);
            #pragma unroll
            for (int j = 0; j < 4; j++) fma2(acc[i][j], ad, w2[j]);
        }
    }
}

// MODE: 0 = embed nodes (K=7 -> g_nh), 1 = embed edges (K=3 -> g_eh)
//       2 = edge update (concat 386 -> MLP -> atomic scatter + residual+LN on eh)
//       3 = node update (concat 258 -> MLP -> residual+LN on nh)
//       4 = decoder (nh -> MLP -> out[N,3])
template <int MODE>
__global__ __launch_bounds__(256, 2)
void gnet_kernel(const float* __restrict__ A0,
                 const float* __restrict__ W0, const float* __restrict__ b0,
                 const float* __restrict__ W1, const float* __restrict__ b1,
                 const float* __restrict__ glob,
                 const int* __restrict__ senders, const int* __restrict__ receivers,
                 const float* __restrict__ ln_s, const float* __restrict__ ln_b,
                 float* __restrict__ outp, int nrows)
{
    extern __shared__ float sm[];
    float* Hs   = sm;            // 128 x 132 (padded) = 16896 floats
    float* As_t = sm + 16896;    // 16 x 128 (k-major, transposed A tile)
    float* Ws   = sm + 18944;    // 16 x 128
    float* scs  = sm + 20992;    // 128
    float* bss  = sm + 21120;    // 128
    int*   sidx = (int*)(sm + 21248);  // 128
    int*   ridx = (int*)(sm + 21376);  // 128

    const int tid = threadIdx.x;
    const int tx = tid & 15;
    const int ty = tid >> 4;
    const int rbase = ty * 8;
    const int cbase = tx * 8;
    const int r0 = blockIdx.x * 128;

    if (MODE == 2 && tid < 128) {
        int e = r0 + tid; if (e >= nrows) e = nrows - 1;
        sidx[tid] = senders[e];
        ridx[tid] = receivers[e];
    }
    if ((MODE == 2 || MODE == 3) && tid < 128) {
        scs[tid] = ln_s[tid];
        bss[tid] = ln_b[tid];
    }

    ull acc[8][4];
    #pragma unroll
    for (int i = 0; i < 8; i++)
        #pragma unroll
        for (int j = 0; j < 4; j++) acc[i][j] = 0ull;

    // ---------------- Layer 1 ----------------
    if (MODE == 0 || MODE == 1) {
        const int KIN = (MODE == 0) ? 7 : 3;
        if (tid < 128) {
            int rg = r0 + tid; if (rg >= nrows) rg = nrows - 1;
            #pragma unroll
            for (int k = 0; k < 8; k++)
                As_t[k * 128 + tid] = (k < KIN) ? A0[rg * KIN + k] : 0.f;
        }
        #pragma unroll
        for (int q = 0; q < 4; q++) {
            int idx = tid + 256 * q;
            Ws[idx] = (idx < KIN * 128) ? W0[idx] : 0.f;
        }
        __syncthreads();
        mma_kt<8>(As_t, Ws, acc, rbase, cbase);
    } else {
        const int NT = (MODE == 2) ? 24 : ((MODE == 3) ? 16 : 8);
        const int row = tid >> 1, half = tid & 1;
        int rg = r0 + row; if (rg >= nrows) rg = nrows - 1;
        for (int kt = 0; kt < NT; kt++) {
            __syncthreads();
            {
                const int k0 = kt * 16;
                const float* src;
                if (MODE == 2) {
                    if (kt < 8)       src = &g_eh[(size_t)rg * 128 + k0];
                    else if (kt < 16) src = &g_nh[sidx[row] * 128 + (k0 - 128)];
                    else              src = &g_nh[ridx[row] * 128 + (k0 - 256)];
                } else if (MODE == 3) {
                    if (kt < 8)       src = &g_nh[rg * 128 + k0];
                    else              src = &g_recv[rg * 128 + (k0 - 128)];
                } else {
                    src = &g_nh[rg * 128 + k0];
                }
                float4 v0 = *(const float4*)(src + half * 8);
                float4 v1 = *(const float4*)(src + half * 8 + 4);
                const int kb = half * 8;
                As_t[(kb + 0) * 128 + row] = v0.x;
                As_t[(kb + 1) * 128 + row] = v0.y;
                As_t[(kb + 2) * 128 + row] = v0.z;
                As_t[(kb + 3) * 128 + row] = v0.w;
                As_t[(kb + 4) * 128 + row] = v1.x;
                As_t[(kb + 5) * 128 + row] = v1.y;
                As_t[(kb + 6) * 128 + row] = v1.z;
                As_t[(kb + 7) * 128 + row] = v1.w;
                const int kr = tid >> 4, seg = tid & 15;
                const float* wsrc = &W0[(k0 + kr) * 128 + seg * 8];
                *(float4*)&Ws[kr * 128 + seg * 8]     = *(const float4*)wsrc;
                *(float4*)&Ws[kr * 128 + seg * 8 + 4] = *(const float4*)(wsrc + 4);
            }
            __syncthreads();
            mma_kt<16>(As_t, Ws, acc, rbase, cbase);
        }
    }

    // Layer-1 epilogue: bias (+globals for MODE 2/3) + gelu -> Hs
    {
        float bb[8];
        {
            float4 bv0 = *(const float4*)&b0[cbase];
            float4 bv1 = *(const float4*)&b0[cbase + 4];
            bb[0] = bv0.x; bb[1] = bv0.y; bb[2] = bv0.z; bb[3] = bv0.w;
            bb[4] = bv1.x; bb[5] = bv1.y; bb[6] = bv1.z; bb[7] = bv1.w;
        }
        if (MODE == 2 || MODE == 3) {
            const int kg = (MODE == 2) ? 384 : 256;
            float g0 = glob[0], g1 = glob[1];
            float4 w0a = *(const float4*)&W0[kg * 128 + cbase];
            float4 w0b = *(const float4*)&W0[kg * 128 + cbase + 4];
            float4 w1a = *(const float4*)&W0[(kg + 1) * 128 + cbase];
            float4 w1b = *(const float4*)&W0[(kg + 1) * 128 + cbase + 4];
            bb[0] += g0 * w0a.x + g1 * w1a.x;  bb[1] += g0 * w0a.y + g1 * w1a.y;
            bb[2] += g0 * w0a.z + g1 * w1a.z;  bb[3] += g0 * w0a.w + g1 * w1a.w;
            bb[4] += g0 * w0b.x + g1 * w1b.x;  bb[5] += g0 * w0b.y + g1 * w1b.y;
            bb[6] += g0 * w0b.z + g1 * w1b.z;  bb[7] += g0 * w0b.w + g1 * w1b.w;
        }
        #pragma unroll
        for (int i = 0; i < 8; i++) {
            int r = rbase + i;
            #pragma unroll
            for (int j2 = 0; j2 < 4; j2++) {
                float2 v = unpk(acc[i][j2]);
                int c = cbase + 2 * j2;
                Hs[r * 132 + c]     = gelu_f(v.x + bb[2 * j2]);
                Hs[r * 132 + c + 1] = gelu_f(v.y + bb[2 * j2 + 1]);
            }
        }
    }

    // ---------------- Layer 2 ----------------
    #pragma unroll
    for (int i = 0; i < 8; i++)
        #pragma unroll
        for (int j = 0; j < 4; j++) acc[i][j] = 0ull;

    if (MODE == 4) {
        __syncthreads();
        for (int idx = tid; idx < 384; idx += 256) Ws[idx] = W1[idx];  // [128,3]
        __syncthreads();
        for (int idx = tid; idx < 384; idx += 256) {
            int rr = idx / 3, o = idx % 3;
            float s = b1[o];
            #pragma unroll 8
            for (int k = 0; k < 128; k++) s += Hs[rr * 132 + k] * Ws[k * 3 + o];
            int rg2 = r0 + rr;
            if (rg2 < nrows) outp[rg2 * 3 + o] = s;
        }
        return;
    }

    for (int kt = 0; kt < 8; kt++) {
        __syncthreads();
        {
            const int k0 = kt * 16;
            const int kr = tid >> 4, seg = tid & 15;
            const float* wsrc = &W1[(k0 + kr) * 128 + seg * 8];
            *(float4*)&Ws[kr * 128 + seg * 8]     = *(const float4*)wsrc;
            *(float4*)&Ws[kr * 128 + seg * 8 + 4] = *(const float4*)(wsrc + 4);
        }
        __syncthreads();
        mma_kt_h(Hs, Ws, acc, rbase, cbase, kt * 16);
    }
    __syncthreads();

    float bb1[8];
    {
        float4 bv0 = *(const float4*)&b1[cbase];
        float4 bv1 = *(const float4*)&b1[cbase + 4];
        bb1[0] = bv0.x; bb1[1] = bv0.y; bb1[2] = bv0.z; bb1[3] = bv0.w;
        bb1[4] = bv1.x; bb1[5] = bv1.y; bb1[6] = bv1.z; bb1[7] = bv1.w;
    }

    if (MODE == 0 || MODE == 1) {
        float* dst = (MODE == 0) ? g_nh : g_eh;
        #pragma unroll
        for (int i = 0; i < 8; i++) {
            int r = rbase + i, rg2 = r0 + r;
            if (rg2 < nrows) {
                #pragma unroll
                for (int j2 = 0; j2 < 4; j2++) {
                    float2 v = unpk(acc[i][j2]);
                    int c = cbase + 2 * j2;
                    float2 st2 = make_float2(v.x + bb1[2 * j2], v.y + bb1[2 * j2 + 1]);
                    *(float2*)&dst[(size_t)rg2 * 128 + c] = st2;
                }
            }
        }
        return;
    }

    // MODE 2/3: new value + residual into Hs; edge mode also scatters to recv
    #pragma unroll
    for (int i = 0; i < 8; i++) {
        int r = rbase + i, rg2 = r0 + r;
        if (rg2 < nrows) {
            #pragma unroll
            for (int j2 = 0; j2 < 4; j2++) {
                float2 v = unpk(acc[i][j2]);
                int c = cbase + 2 * j2;
                float va = v.x + bb1[2 * j2];
                float vb = v.y + bb1[2 * j2 + 1];
                if (MODE == 2) {
                    atomicAdd(&g_recv[ridx[r] * 128 + c], va);
                    atomicAdd(&g_recv[ridx[r] * 128 + c + 1], vb);
                    float2 e = *(const float2*)&g_eh[(size_t)rg2 * 128 + c];
                    Hs[r * 132 + c]     = e.x + va;
                    Hs[r * 132 + c + 1] = e.y + vb;
                } else {
                    float2 nv = *(const float2*)&g_nh[rg2 * 128 + c];
                    Hs[r * 132 + c]     = nv.x + va;
                    Hs[r * 132 + c + 1] = nv.y + vb;
                }
            }
        }
    }
    __syncthreads();

    // Fused LayerNorm over each 128-wide row
    const int warp = tid >> 5, lane = tid & 31;
    for (int rr = warp; rr < 128; rr += 8) {
        int rg2 = r0 + rr;
        float4 v = *(float4*)&Hs[rr * 132 + lane * 4];
        float s = v.x + v.y + v.z + v.w;
        #pragma unroll
        for (int o = 16; o > 0; o >>= 1) s += __shfl_xor_sync(0xffffffffu, s, o);
        float mean = s * (1.f / 128.f);
        float dx = v.x - mean, dy = v.y - mean, dz = v.z - mean, dw = v.w - mean;
        float q = dx * dx + dy * dy + dz * dz + dw * dw;
        #pragma unroll
        for (int o = 16; o > 0; o >>= 1) q += __shfl_xor_sync(0xffffffffu, q, o);
        float inv = rsqrtf(q * (1.f / 128.f) + 1e-6f);
        float4 sc = *(float4*)&scs[lane * 4];
        float4 bbv = *(float4*)&bss[lane * 4];
        float4 o4;
        o4.x = dx * inv * sc.x + bbv.x;
        o4.y = dy * inv * sc.y + bbv.y;
        o4.z = dz * inv * sc.z + bbv.z;
        o4.w = dw * inv * sc.w + bbv.w;
        if (rg2 < nrows) {
            float* dst = (MODE == 2) ? &g_eh[(size_t)rg2 * 128] : &g_nh[rg2 * 128];
            *(float4*)&dst[lane * 4] = o4;
        }
    }
}

__global__ void zero_recv_kernel() {
    int i = blockIdx.x * blockDim.x + threadIdx.x;
    if (i < NN * 128) g_recv[i] = 0.f;
}

extern "C" void kernel_launch(void* const* d_in, const int* in_sizes, int n_in,
                              void* d_out, int out_size)
{
    const float* nodes   = (const float*)d_in[0];
    const float* edges   = (const float*)d_in[1];
    const float* glob    = (const float*)d_in[2];
    const int*   senders = (const int*)d_in[3];
    const int*   recvrs  = (const int*)d_in[4];
    const float* ne_W0 = (const float*)d_in[5],  *ne_b0 = (const float*)d_in[6];
    const float* ne_W1 = (const float*)d_in[7],  *ne_b1 = (const float*)d_in[8];
    const float* ee_W0 = (const float*)d_in[9],  *ee_b0 = (const float*)d_in[10];
    const float* ee_W1 = (const float*)d_in[11], *ee_b1 = (const float*)d_in[12];
    const float* eu_W0 = (const float*)d_in[13], *eu_b0 = (const float*)d_in[14];
    const float* eu_W1 = (const float*)d_in[15], *eu_b1 = (const float*)d_in[16];
    const float* nu_W0 = (const float*)d_in[17], *nu_b0 = (const float*)d_in[18];
    const float* nu_W1 = (const float*)d_in[19], *nu_b1 = (const float*)d_in[20];
    const float* ln_s  = (const float*)d_in[21], *ln_b  = (const float*)d_in[22];
    const float* dc_W0 = (const float*)d_in[23], *dc_b0 = (const float*)d_in[24];
    const float* dc_W1 = (const float*)d_in[25], *dc_b1 = (const float*)d_in[26];
    float* out = (float*)d_out;

    const int SMEM = 21504 * (int)sizeof(float);  // 86016 B dynamic smem
    cudaFuncSetAttribute(gnet_kernel<0>, cudaFuncAttributeMaxDynamicSharedMemorySize, SMEM);
    cudaFuncSetAttribute(gnet_kernel<1>, cudaFuncAttributeMaxDynamicSharedMemorySize, SMEM);
    cudaFuncSetAttribute(gnet_kernel<2>, cudaFuncAttributeMaxDynamicSharedMemorySize, SMEM);
    cudaFuncSetAttribute(gnet_kernel<3>, cudaFuncAttributeMaxDynamicSharedMemorySize, SMEM);
    cudaFuncSetAttribute(gnet_kernel<4>, cudaFuncAttributeMaxDynamicSharedMemorySize, SMEM);

    const int gN = (NN + 127) / 128;   // 391
    const int gE = (EE + 127) / 128;   // 3907

    // Embeds
    gnet_kernel<0><<<gN, 256, SMEM>>>(nodes, ne_W0, ne_b0, ne_W1, ne_b1,
                                      nullptr, nullptr, nullptr, nullptr, nullptr, nullptr, NN);
    gnet_kernel<1><<<gE, 256, SMEM>>>(edges, ee_W0, ee_b0, ee_W1, ee_b1,
                                      nullptr, nullptr, nullptr, nullptr, nullptr, nullptr, EE);

    // Message-passing steps
    for (int s = 0; s < 2; s++) {
        zero_recv_kernel<<<(NN * 128 + 255) / 256, 256>>>();
        gnet_kernel<2><<<gE, 256, SMEM>>>(nullptr,
                                          eu_W0 + s * 386 * 128, eu_b0 + s * 128,
                                          eu_W1 + s * 128 * 128, eu_b1 + s * 128,
                                          glob, senders, recvrs, ln_s, ln_b, nullptr, EE);
        gnet_kernel<3><<<gN, 256, SMEM>>>(nullptr,
                                          nu_W0 + s * 258 * 128, nu_b0 + s * 128,
                                          nu_W1 + s * 128 * 128, nu_b1 + s * 128,
                                          glob, nullptr, nullptr, ln_s, ln_b, nullptr, NN);
    }

    // Decoder
    gnet_kernel<4><<<gN, 256, SMEM>>>(nullptr, dc_W0, dc_b0, dc_W1, dc_b1,
                                      nullptr, nullptr, nullptr, nullptr, nullptr, out, NN);
}